// round 15
// baseline (speedup 1.0000x reference)
#include <cuda_runtime.h>
#include <cuda_bf16.h>
#include <cstdint>

// VQ codebook quantization via mma.sync bf16 (3-term split, fp32-exact).
//   s[n,k] = z[n]·e[k] - 0.5*||e[k]||^2 ; idx[n] = argmax_k s ; out = e[idx]
// N=65536, D=64, K=1024. Output: [N*D quantized][N indices-as-float].
//
// R15: occupancy play. 16 rows/warp (A=32 regs), 2 accumulator sets
// (dh pre-biased with -cn, dc for both correction terms), target 3 CTAs/SM
// (24 warps/SM, 6/SMSP) so LDSM latency + fold chains hide across warps.
// Staging = R13's proven synchronous scheme (cp.async of R14 regressed).

#define DDIM 64
#define TKC  128
#define EPB  144          // bytes per e row in smem (conflict-free ldmatrix)
#define KMAX 1024

__device__ float g_cnorm[KMAX];
__device__ __align__(16) __nv_bfloat16 g_eh[KMAX * DDIM];
__device__ __align__(16) __nv_bfloat16 g_el[KMAX * DDIM];

__global__ void prep_kernel(const float* __restrict__ emb, int K) {
    int k = blockIdx.x * blockDim.x + threadIdx.x;
    if (k < K) {
        float s = 0.f;
#pragma unroll
        for (int d = 0; d < DDIM; d++) {
            float v = emb[(size_t)k * DDIM + d];
            s += v * v;
            __nv_bfloat16 h = __float2bfloat16(v);
            g_eh[(size_t)k * DDIM + d] = h;
            g_el[(size_t)k * DDIM + d] =
                __float2bfloat16(v - __bfloat162float(h));
        }
        g_cnorm[k] = 0.5f * s;
    }
}

__device__ __forceinline__ uint32_t smem_u32(const void* p) {
    uint32_t a;
    asm("{ .reg .u64 t; cvta.to.shared.u64 t, %1; cvt.u32.u64 %0, t; }"
        : "=r"(a) : "l"(p));
    return a;
}
__device__ __forceinline__ uint32_t pack_bf16x2(float x, float y) {
    __nv_bfloat162 h;
    h.x = __float2bfloat16(x);
    h.y = __float2bfloat16(y);
    return *reinterpret_cast<uint32_t*>(&h);
}
__device__ __forceinline__ uint32_t pack_res(float x, float y, uint32_t hp) {
    __nv_bfloat162 h = *reinterpret_cast<__nv_bfloat162*>(&hp);
    __nv_bfloat162 l;
    l.x = __float2bfloat16(x - __bfloat162float(h.x));
    l.y = __float2bfloat16(y - __bfloat162float(h.y));
    return *reinterpret_cast<uint32_t*>(&l);
}
#define MMA16816(d, a, b0, b1) \
    asm volatile( \
        "mma.sync.aligned.m16n8k16.row.col.f32.bf16.bf16.f32 " \
        "{%0,%1,%2,%3},{%4,%5,%6,%7},{%8,%9},{%0,%1,%2,%3};" \
        : "+f"((d)[0]), "+f"((d)[1]), "+f"((d)[2]), "+f"((d)[3]) \
        : "r"((a)[0]), "r"((a)[1]), "r"((a)[2]), "r"((a)[3]), "r"(b0), "r"(b1))
#define LDMX4(r0, r1, r2, r3, a) \
    asm volatile("ldmatrix.sync.aligned.m8n8.x4.shared.b16 {%0,%1,%2,%3}, [%4];" \
                 : "=r"(r0), "=r"(r1), "=r"(r2), "=r"(r3) : "r"(a))

__global__ __launch_bounds__(256, 3)
void vq_kernel(const float* __restrict__ z, const float* __restrict__ emb,
               float* __restrict__ out, int N, int K, int write_idx) {
    __shared__ float cns[KMAX];                       // 4 KB
    __shared__ __align__(16) char eh_sm[TKC * EPB];   // 18 KB
    __shared__ __align__(16) char el_sm[TKC * EPB];   // 18 KB
    __shared__ int finalIdx[128];

    const int tid = threadIdx.x;
    const int wid = tid >> 5;
    const int lane = tid & 31;
    const int qid = lane >> 2;       // 0..7
    const int qsub = lane & 3;       // 0..3
    const int rowBase = blockIdx.x * 128;

    // ---- A fragments (zh/zl) for rows (r0, r0+8), 4 k-steps, from gmem ----
    uint32_t ah[4][4], al[4][4];
    {
        const int r0 = rowBase + wid * 16 + qid;
        const int r1 = r0 + 8;
#pragma unroll
        for (int ks = 0; ks < 4; ks++) {
            int k0 = ks * 16 + qsub * 2;
            float2 v00 = *reinterpret_cast<const float2*>(z + (size_t)r0 * DDIM + k0);
            float2 v01 = *reinterpret_cast<const float2*>(z + (size_t)r0 * DDIM + k0 + 8);
            float2 v10 = *reinterpret_cast<const float2*>(z + (size_t)r1 * DDIM + k0);
            float2 v11 = *reinterpret_cast<const float2*>(z + (size_t)r1 * DDIM + k0 + 8);
            ah[ks][0] = pack_bf16x2(v00.x, v00.y);
            ah[ks][1] = pack_bf16x2(v10.x, v10.y);
            ah[ks][2] = pack_bf16x2(v01.x, v01.y);
            ah[ks][3] = pack_bf16x2(v11.x, v11.y);
            al[ks][0] = pack_res(v00.x, v00.y, ah[ks][0]);
            al[ks][1] = pack_res(v10.x, v10.y, ah[ks][1]);
            al[ks][2] = pack_res(v01.x, v01.y, ah[ks][2]);
            al[ks][3] = pack_res(v11.x, v11.y, ah[ks][3]);
        }
    }
    for (int i = tid; i < K; i += 256) cns[i] = g_cnorm[i];

    const uint32_t eh_b = smem_u32(eh_sm);
    const uint32_t el_b = smem_u32(el_sm);
    const uint32_t lm_lane = (lane & 7) * EPB + (lane >> 3) * 16;

    const float NEG = -3.402823466e38f;
    float best[2] = {NEG, NEG};      // rows qid, qid+8
    int bidx[2] = {0, 0};

    const int nchunks = K / TKC;     // 8
    for (int c = 0; c < nchunks; c++) {
        __syncthreads();
        // stage e chunk: 128 codes x 8 uint4 per term (pitch 144 B)
        {
            const uint4* sh = reinterpret_cast<const uint4*>(
                g_eh + (size_t)c * TKC * DDIM);
            const uint4* sl = reinterpret_cast<const uint4*>(
                g_el + (size_t)c * TKC * DDIM);
#pragma unroll
            for (int t = 0; t < 4; t++) {
                int u = tid + t * 256;
                int code = u >> 3, q = u & 7;
                *reinterpret_cast<uint4*>(eh_sm + code * EPB + q * 16) =
                    sh[code * 8 + q];
                *reinterpret_cast<uint4*>(el_sm + code * EPB + q * 16) =
                    sl[code * 8 + q];
            }
        }
        __syncthreads();

#pragma unroll
        for (int nt = 0; nt < TKC / 8; nt++) {   // 16 n-tiles of 8 codes
            uint32_t lm_off = nt * 8 * EPB + lm_lane;
            uint32_t bh[8], bl[8];
            LDMX4(bh[0], bh[1], bh[2], bh[3], eh_b + lm_off);        // k 0..31
            LDMX4(bh[4], bh[5], bh[6], bh[7], eh_b + lm_off + 64);   // k 32..63
            LDMX4(bl[0], bl[1], bl[2], bl[3], el_b + lm_off);
            LDMX4(bl[4], bl[5], bl[6], bl[7], el_b + lm_off + 64);

            int code0 = c * TKC + nt * 8 + qsub * 2;
            float2 cn = *reinterpret_cast<const float2*>(&cns[code0]);
            float dh[4] = {-cn.x, -cn.y, -cn.x, -cn.y};
            float dc[4] = {0, 0, 0, 0};
#pragma unroll
            for (int ks = 0; ks < 4; ks++) {
                MMA16816(dh, ah[ks], bh[2*ks], bh[2*ks+1]);   // zh·eh - cn
                MMA16816(dc, al[ks], bh[2*ks], bh[2*ks+1]);   // zl·eh
                MMA16816(dc, ah[ks], bl[2*ks], bl[2*ks+1]);   // zh·el
            }

            float s;
            s = dh[0] + dc[0];
            if (s > best[0]) { best[0] = s; bidx[0] = code0; }
            s = dh[1] + dc[1];
            if (s > best[0]) { best[0] = s; bidx[0] = code0 + 1; }
            s = dh[2] + dc[2];
            if (s > best[1]) { best[1] = s; bidx[1] = code0; }
            s = dh[3] + dc[3];
            if (s > best[1]) { best[1] = s; bidx[1] = code0 + 1; }
        }
    }

    // ---- quad-lane reduce (rows live in lanes 4q..4q+3), index tie-break ----
#pragma unroll
    for (int off = 1; off < 4; off <<= 1) {
#pragma unroll
        for (int r = 0; r < 2; r++) {
            float v = __shfl_xor_sync(0xFFFFFFFFu, best[r], off);
            int i = __shfl_xor_sync(0xFFFFFFFFu, bidx[r], off);
            if (v > best[r] || (v == best[r] && i < bidx[r])) {
                best[r] = v; bidx[r] = i;
            }
        }
    }
    if (qsub == 0) {
        finalIdx[wid * 16 + qid] = bidx[0];
        finalIdx[wid * 16 + qid + 8] = bidx[1];
    }
    __syncthreads();

    if (write_idx && tid < 128)
        out[(size_t)N * DDIM + rowBase + tid] = (float)finalIdx[tid];

    // ---- gather quantized rows (emb rows L2-hot) ----
#pragma unroll
    for (int t = 0; t < 8; t++) {
        int idx = tid + t * 256;
        int row = idx >> 4;
        int c4 = idx & 15;
        float4 v = reinterpret_cast<const float4*>(
            emb + (size_t)finalIdx[row] * DDIM)[c4];
        reinterpret_cast<float4*>(out + (size_t)(rowBase + row) * DDIM)[c4] = v;
    }
}

extern "C" void kernel_launch(void* const* d_in, const int* in_sizes, int n_in,
                              void* d_out, int out_size) {
    const float* z = (const float*)d_in[0];
    const float* emb = (const float*)d_in[1];
    if (n_in >= 2 && in_sizes[1] > in_sizes[0]) {
        const float* t = z; z = emb; emb = t;
    }
    int zsize = in_sizes[0], esize = in_sizes[1];
    if (esize > zsize) { int t = zsize; zsize = esize; esize = t; }

    int N = zsize / DDIM;   // 65536
    int K = esize / DDIM;   // 1024
    float* out = (float*)d_out;
    int write_idx = (out_size >= N * DDIM + N) ? 1 : 0;

    prep_kernel<<<(K + 255) / 256, 256>>>(emb, K);
    vq_kernel<<<N / 128, 256>>>(z, emb, out, N, K, write_idx);
}

// round 16
// speedup vs baseline: 1.0933x; 1.0933x over previous
#include <cuda_runtime.h>
#include <cuda_bf16.h>
#include <cstdint>

// VQ codebook quantization via mma.sync bf16 (3-term split, fp32-exact).
//   s[n,k] = z[n]·e[k] - 0.5*||e[k]||^2 ; idx[n] = argmax_k s ; out = e[idx]
// N=65536, D=64, K=1024. Output: [N*D quantized][N indices-as-float].
//
// R16 = R13 mainloop (best measured) + fused e-split/cnorm staging:
// no prep kernel, no __device__ scratch. Each chunk stages straight from
// fp32 emb (2 threads/code, on-the-fly bf16 hi/lo split + norm via shfl).
// Per tile: bl LDSM at top; 16 bh-MMAs; prefetch bh' under bl-MMAs;
// -cn baked into dh accumulator init.

#define DDIM 64
#define TKC  128
#define EPB  144          // bytes per e row in smem (conflict-free ldmatrix)

__device__ __forceinline__ uint32_t smem_u32(const void* p) {
    uint32_t a;
    asm("{ .reg .u64 t; cvta.to.shared.u64 t, %1; cvt.u32.u64 %0, t; }"
        : "=r"(a) : "l"(p));
    return a;
}
__device__ __forceinline__ uint32_t pack_bf16x2(float x, float y) {
    __nv_bfloat162 h;
    h.x = __float2bfloat16(x);
    h.y = __float2bfloat16(y);
    return *reinterpret_cast<uint32_t*>(&h);
}
__device__ __forceinline__ uint32_t pack_res(float x, float y, uint32_t hp) {
    __nv_bfloat162 h = *reinterpret_cast<__nv_bfloat162*>(&hp);
    __nv_bfloat162 l;
    l.x = __float2bfloat16(x - __bfloat162float(h.x));
    l.y = __float2bfloat16(y - __bfloat162float(h.y));
    return *reinterpret_cast<uint32_t*>(&l);
}
#define MMA16816(d, a, b0, b1) \
    asm volatile( \
        "mma.sync.aligned.m16n8k16.row.col.f32.bf16.bf16.f32 " \
        "{%0,%1,%2,%3},{%4,%5,%6,%7},{%8,%9},{%0,%1,%2,%3};" \
        : "+f"((d)[0]), "+f"((d)[1]), "+f"((d)[2]), "+f"((d)[3]) \
        : "r"((a)[0]), "r"((a)[1]), "r"((a)[2]), "r"((a)[3]), "r"(b0), "r"(b1))
#define LDMX4(r0, r1, r2, r3, a) \
    asm volatile("ldmatrix.sync.aligned.m8n8.x4.shared.b16 {%0,%1,%2,%3}, [%4];" \
                 : "=r"(r0), "=r"(r1), "=r"(r2), "=r"(r3) : "r"(a))

// build A fragments for rows (r0, r0+8), 4 k-steps, from gmem z
__device__ __forceinline__ void build_afrag(const float* z, int r0, int qsub,
                                            uint32_t ah[4][4], uint32_t al[4][4]) {
    const int r1 = r0 + 8;
#pragma unroll
    for (int ks = 0; ks < 4; ks++) {
        int k0 = ks * 16 + qsub * 2;
        float2 v00 = *reinterpret_cast<const float2*>(z + (size_t)r0 * DDIM + k0);
        float2 v01 = *reinterpret_cast<const float2*>(z + (size_t)r0 * DDIM + k0 + 8);
        float2 v10 = *reinterpret_cast<const float2*>(z + (size_t)r1 * DDIM + k0);
        float2 v11 = *reinterpret_cast<const float2*>(z + (size_t)r1 * DDIM + k0 + 8);
        ah[ks][0] = pack_bf16x2(v00.x, v00.y);
        ah[ks][1] = pack_bf16x2(v10.x, v10.y);
        ah[ks][2] = pack_bf16x2(v01.x, v01.y);
        ah[ks][3] = pack_bf16x2(v11.x, v11.y);
        al[ks][0] = pack_res(v00.x, v00.y, ah[ks][0]);
        al[ks][1] = pack_res(v10.x, v10.y, ah[ks][1]);
        al[ks][2] = pack_res(v01.x, v01.y, ah[ks][2]);
        al[ks][3] = pack_res(v11.x, v11.y, ah[ks][3]);
    }
}

__global__ __launch_bounds__(256, 2)
void vq_kernel(const float* __restrict__ z, const float* __restrict__ emb,
               float* __restrict__ out, int N, int K, int write_idx) {
    __shared__ float cns[TKC];                        // per-chunk norms
    __shared__ __align__(16) char eh_sm[TKC * EPB];   // 18 KB
    __shared__ __align__(16) char el_sm[TKC * EPB];   // 18 KB
    __shared__ int finalIdx[256];

    const int tid = threadIdx.x;
    const int wid = tid >> 5;
    const int lane = tid & 31;
    const int qid = lane >> 2;
    const int qsub = lane & 3;
    const int rowBase = blockIdx.x * 256;

    // ---- A fragments for two 16-row tiles (32 rows per warp) ----
    uint32_t ah0[4][4], al0[4][4], ah1[4][4], al1[4][4];
    const int r0 = rowBase + wid * 32 + qid;
    build_afrag(z, r0, qsub, ah0, al0);
    build_afrag(z, r0 + 16, qsub, ah1, al1);

    const uint32_t eh_b = smem_u32(eh_sm);
    const uint32_t el_b = smem_u32(el_sm);
    const uint32_t lm_lane = (lane & 7) * EPB + (lane >> 3) * 16;

    // staging geometry: 2 threads per code, 32 dims each
    const int s_code = tid >> 1;          // 0..127
    const int s_half = tid & 1;           // 0: dims 0..31, 1: dims 32..63

    const float NEG = -3.402823466e38f;
    float best[4] = {NEG, NEG, NEG, NEG};   // rows qid, qid+8, qid+16, qid+24
    int bidx[4] = {0, 0, 0, 0};

    const int nchunks = K / TKC;   // 8
    for (int c = 0; c < nchunks; c++) {
        __syncthreads();
        // ---- fused staging: fp32 emb -> bf16 hi/lo split + code norm ----
        {
            const float4* src = reinterpret_cast<const float4*>(
                emb + (size_t)(c * TKC + s_code) * DDIM + s_half * 32);
            char* dh_p = eh_sm + s_code * EPB + s_half * 64;
            char* dl_p = el_sm + s_code * EPB + s_half * 64;
            float nrm = 0.f;
#pragma unroll
            for (int q = 0; q < 8; q++) {
                float4 v = src[q];
                nrm += v.x * v.x + v.y * v.y + v.z * v.z + v.w * v.w;
                uint32_t h0 = pack_bf16x2(v.x, v.y);
                uint32_t h1 = pack_bf16x2(v.z, v.w);
                uint32_t l0 = pack_res(v.x, v.y, h0);
                uint32_t l1 = pack_res(v.z, v.w, h1);
                uint2 hp; hp.x = h0; hp.y = h1;
                uint2 lp; lp.x = l0; lp.y = l1;
                *reinterpret_cast<uint2*>(dh_p + q * 8) = hp;
                *reinterpret_cast<uint2*>(dl_p + q * 8) = lp;
            }
            nrm += __shfl_xor_sync(0xFFFFFFFFu, nrm, 1);
            if (s_half == 0) cns[s_code] = 0.5f * nrm;
        }
        __syncthreads();

        // preload bh for nt=0
        uint32_t bh[8];
        LDMX4(bh[0], bh[1], bh[2], bh[3], eh_b + lm_lane);
        LDMX4(bh[4], bh[5], bh[6], bh[7], eh_b + lm_lane + 64);

#pragma unroll
        for (int nt = 0; nt < TKC / 8; nt++) {   // 16 n-tiles of 8 codes
            uint32_t bl[8];
            uint32_t lm_off = nt * 8 * EPB + lm_lane;
            LDMX4(bl[0], bl[1], bl[2], bl[3], el_b + lm_off);
            LDMX4(bl[4], bl[5], bl[6], bl[7], el_b + lm_off + 64);

            int lc0 = nt * 8 + qsub * 2;
            int code0 = c * TKC + lc0;
            float2 cn = *reinterpret_cast<const float2*>(&cns[lc0]);
            float dh0[4] = {-cn.x, -cn.y, -cn.x, -cn.y};
            float dh1[4] = {-cn.x, -cn.y, -cn.x, -cn.y};
            float dc0[4] = {0, 0, 0, 0};
            float dc1[4] = {0, 0, 0, 0};

            // phase 1: 16 bh-consuming MMAs (zh·eh, zl·eh)
#pragma unroll
            for (int ks = 0; ks < 4; ks++) {
                MMA16816(dh0, ah0[ks], bh[2*ks], bh[2*ks+1]);
                MMA16816(dh1, ah1[ks], bh[2*ks], bh[2*ks+1]);
                MMA16816(dc0, al0[ks], bh[2*ks], bh[2*ks+1]);
                MMA16816(dc1, al1[ks], bh[2*ks], bh[2*ks+1]);
            }
            // prefetch next tile's bh under the bl-MMA burst
            if (nt + 1 < TKC / 8) {
                uint32_t lm_n = (nt + 1) * 8 * EPB + lm_lane;
                LDMX4(bh[0], bh[1], bh[2], bh[3], eh_b + lm_n);
                LDMX4(bh[4], bh[5], bh[6], bh[7], eh_b + lm_n + 64);
            }
            // phase 2: 8 bl-consuming MMAs (zh·el)
#pragma unroll
            for (int ks = 0; ks < 4; ks++) {
                MMA16816(dc0, ah0[ks], bl[2*ks], bl[2*ks+1]);
                MMA16816(dc1, ah1[ks], bl[2*ks], bl[2*ks+1]);
            }

            // fold (cn already folded into dh)
            float s;
            s = dh0[0] + dc0[0];
            if (s > best[0]) { best[0] = s; bidx[0] = code0; }
            s = dh0[1] + dc0[1];
            if (s > best[0]) { best[0] = s; bidx[0] = code0 + 1; }
            s = dh0[2] + dc0[2];
            if (s > best[1]) { best[1] = s; bidx[1] = code0; }
            s = dh0[3] + dc0[3];
            if (s > best[1]) { best[1] = s; bidx[1] = code0 + 1; }
            s = dh1[0] + dc1[0];
            if (s > best[2]) { best[2] = s; bidx[2] = code0; }
            s = dh1[1] + dc1[1];
            if (s > best[2]) { best[2] = s; bidx[2] = code0 + 1; }
            s = dh1[2] + dc1[2];
            if (s > best[3]) { best[3] = s; bidx[3] = code0; }
            s = dh1[3] + dc1[3];
            if (s > best[3]) { best[3] = s; bidx[3] = code0 + 1; }
        }
    }

    // ---- quad-lane reduce (rows live in lanes 4q..4q+3), index tie-break ----
#pragma unroll
    for (int off = 1; off < 4; off <<= 1) {
#pragma unroll
        for (int r = 0; r < 4; r++) {
            float v = __shfl_xor_sync(0xFFFFFFFFu, best[r], off);
            int i = __shfl_xor_sync(0xFFFFFFFFu, bidx[r], off);
            if (v > best[r] || (v == best[r] && i < bidx[r])) {
                best[r] = v; bidx[r] = i;
            }
        }
    }
    if (qsub == 0) {
#pragma unroll
        for (int r = 0; r < 4; r++)
            finalIdx[wid * 32 + qid + r * 8] = bidx[r];
    }
    __syncthreads();

    if (write_idx)
        out[(size_t)N * DDIM + rowBase + tid] = (float)finalIdx[tid];

    // ---- gather quantized rows (emb rows L2-hot) ----
#pragma unroll
    for (int t = 0; t < 16; t++) {
        int idx = tid + t * 256;
        int row = idx >> 4;
        int c4 = idx & 15;
        float4 v = reinterpret_cast<const float4*>(
            emb + (size_t)finalIdx[row] * DDIM)[c4];
        reinterpret_cast<float4*>(out + (size_t)(rowBase + row) * DDIM)[c4] = v;
    }
}

extern "C" void kernel_launch(void* const* d_in, const int* in_sizes, int n_in,
                              void* d_out, int out_size) {
    const float* z = (const float*)d_in[0];
    const float* emb = (const float*)d_in[1];
    if (n_in >= 2 && in_sizes[1] > in_sizes[0]) {
        const float* t = z; z = emb; emb = t;
    }
    int zsize = in_sizes[0], esize = in_sizes[1];
    if (esize > zsize) { int t = zsize; zsize = esize; esize = t; }

    int N = zsize / DDIM;   // 65536
    int K = esize / DDIM;   // 1024
    float* out = (float*)d_out;
    int write_idx = (out_size >= N * DDIM + N) ? 1 : 0;

    vq_kernel<<<N / 256, 256>>>(z, emb, out, N, K, write_idx);
}

// round 17
// speedup vs baseline: 1.1052x; 1.0108x over previous
#include <cuda_runtime.h>
#include <cuda_bf16.h>
#include <cstdint>

// VQ codebook quantization via mma.sync bf16 (3-term split, fp32-exact).
//   s[n,k] = z[n]·e[k] - 0.5*||e[k]||^2 ; idx[n] = argmax_k s ; out = e[idx]
// N=65536, D=64, K=1024. Output: [N*D quantized][N indices-as-float].
//
// R17 = R16 + deferred fold: accumulator sets ping-pong by tile parity and
// tile t's fold executes during tile t+1's MMA burst (inputs long retired ->
// no drain). bh/bl share one 8-reg buffer to stay under the 128-reg cap.

#define DDIM 64
#define TKC  128
#define EPB  144          // bytes per e row in smem (conflict-free ldmatrix)

__device__ __forceinline__ uint32_t smem_u32(const void* p) {
    uint32_t a;
    asm("{ .reg .u64 t; cvta.to.shared.u64 t, %1; cvt.u32.u64 %0, t; }"
        : "=r"(a) : "l"(p));
    return a;
}
__device__ __forceinline__ uint32_t pack_bf16x2(float x, float y) {
    __nv_bfloat162 h;
    h.x = __float2bfloat16(x);
    h.y = __float2bfloat16(y);
    return *reinterpret_cast<uint32_t*>(&h);
}
__device__ __forceinline__ uint32_t pack_res(float x, float y, uint32_t hp) {
    __nv_bfloat162 h = *reinterpret_cast<__nv_bfloat162*>(&hp);
    __nv_bfloat162 l;
    l.x = __float2bfloat16(x - __bfloat162float(h.x));
    l.y = __float2bfloat16(y - __bfloat162float(h.y));
    return *reinterpret_cast<uint32_t*>(&l);
}
#define MMA16816(d, a, b0, b1) \
    asm volatile( \
        "mma.sync.aligned.m16n8k16.row.col.f32.bf16.bf16.f32 " \
        "{%0,%1,%2,%3},{%4,%5,%6,%7},{%8,%9},{%0,%1,%2,%3};" \
        : "+f"((d)[0]), "+f"((d)[1]), "+f"((d)[2]), "+f"((d)[3]) \
        : "r"((a)[0]), "r"((a)[1]), "r"((a)[2]), "r"((a)[3]), "r"(b0), "r"(b1))
#define LDMX4(r0, r1, r2, r3, a) \
    asm volatile("ldmatrix.sync.aligned.m8n8.x4.shared.b16 {%0,%1,%2,%3}, [%4];" \
                 : "=r"(r0), "=r"(r1), "=r"(r2), "=r"(r3) : "r"(a))

__device__ __forceinline__ void build_afrag(const float* z, int r0, int qsub,
                                            uint32_t ah[4][4], uint32_t al[4][4]) {
    const int r1 = r0 + 8;
#pragma unroll
    for (int ks = 0; ks < 4; ks++) {
        int k0 = ks * 16 + qsub * 2;
        float2 v00 = *reinterpret_cast<const float2*>(z + (size_t)r0 * DDIM + k0);
        float2 v01 = *reinterpret_cast<const float2*>(z + (size_t)r0 * DDIM + k0 + 8);
        float2 v10 = *reinterpret_cast<const float2*>(z + (size_t)r1 * DDIM + k0);
        float2 v11 = *reinterpret_cast<const float2*>(z + (size_t)r1 * DDIM + k0 + 8);
        ah[ks][0] = pack_bf16x2(v00.x, v00.y);
        ah[ks][1] = pack_bf16x2(v10.x, v10.y);
        ah[ks][2] = pack_bf16x2(v01.x, v01.y);
        ah[ks][3] = pack_bf16x2(v11.x, v11.y);
        al[ks][0] = pack_res(v00.x, v00.y, ah[ks][0]);
        al[ks][1] = pack_res(v10.x, v10.y, ah[ks][1]);
        al[ks][2] = pack_res(v01.x, v01.y, ah[ks][2]);
        al[ks][3] = pack_res(v11.x, v11.y, ah[ks][3]);
    }
}

__global__ __launch_bounds__(256, 2)
void vq_kernel(const float* __restrict__ z, const float* __restrict__ emb,
               float* __restrict__ out, int N, int K, int write_idx) {
    __shared__ float cns[TKC];
    __shared__ __align__(16) char eh_sm[TKC * EPB];   // 18 KB
    __shared__ __align__(16) char el_sm[TKC * EPB];   // 18 KB
    __shared__ int finalIdx[256];

    const int tid = threadIdx.x;
    const int wid = tid >> 5;
    const int lane = tid & 31;
    const int qid = lane >> 2;
    const int qsub = lane & 3;
    const int rowBase = blockIdx.x * 256;

    uint32_t ah0[4][4], al0[4][4], ah1[4][4], al1[4][4];
    const int r0 = rowBase + wid * 32 + qid;
    build_afrag(z, r0, qsub, ah0, al0);
    build_afrag(z, r0 + 16, qsub, ah1, al1);

    const uint32_t eh_b = smem_u32(eh_sm);
    const uint32_t el_b = smem_u32(el_sm);
    const uint32_t lm_lane = (lane & 7) * EPB + (lane >> 3) * 16;

    const int s_code = tid >> 1;
    const int s_half = tid & 1;

    const float NEG = -3.402823466e38f;
    float best[4] = {NEG, NEG, NEG, NEG};
    int bidx[4] = {0, 0, 0, 0};

    // ping-pong accumulator sets; B starts as a harmless (-inf) dummy
    float Adh0[4], Adh1[4], Adc0[4], Adc1[4];
    float Bdh0[4], Bdh1[4], Bdc0[4], Bdc1[4];
    int codeA = 0, codeB = 0;
#pragma unroll
    for (int i = 0; i < 4; i++) {
        Bdh0[i] = NEG; Bdh1[i] = NEG; Bdc0[i] = 0.f; Bdc1[i] = 0.f;
    }

#define TILE_BODY(Xdh0, Xdh1, Xdc0, Xdc1, Xcode, Ydh0, Ydh1, Ydc0, Ydc1, Ycode) \
    do {                                                                        \
        uint32_t b[8];                                                          \
        uint32_t lm_off = nt * 8 * EPB + lm_lane;                               \
        LDMX4(b[0], b[1], b[2], b[3], eh_b + lm_off);                           \
        LDMX4(b[4], b[5], b[6], b[7], eh_b + lm_off + 64);                      \
        int lc0 = nt * 8 + qsub * 2;                                            \
        Xcode = c * TKC + lc0;                                                  \
        float2 cn = *reinterpret_cast<const float2*>(&cns[lc0]);                \
        Xdh0[0] = -cn.x; Xdh0[1] = -cn.y; Xdh0[2] = -cn.x; Xdh0[3] = -cn.y;     \
        Xdh1[0] = -cn.x; Xdh1[1] = -cn.y; Xdh1[2] = -cn.x; Xdh1[3] = -cn.y;     \
        Xdc0[0] = 0.f; Xdc0[1] = 0.f; Xdc0[2] = 0.f; Xdc0[3] = 0.f;             \
        Xdc1[0] = 0.f; Xdc1[1] = 0.f; Xdc1[2] = 0.f; Xdc1[3] = 0.f;             \
        _Pragma("unroll")                                                       \
        for (int ks = 0; ks < 4; ks++) {                                        \
            MMA16816(Xdh0, ah0[ks], b[2*ks], b[2*ks+1]);                        \
            MMA16816(Xdh1, ah1[ks], b[2*ks], b[2*ks+1]);                        \
            MMA16816(Xdc0, al0[ks], b[2*ks], b[2*ks+1]);                        \
            MMA16816(Xdc1, al1[ks], b[2*ks], b[2*ks+1]);                        \
        }                                                                       \
        LDMX4(b[0], b[1], b[2], b[3], el_b + lm_off);                           \
        LDMX4(b[4], b[5], b[6], b[7], el_b + lm_off + 64);                      \
        _Pragma("unroll")                                                       \
        for (int ks = 0; ks < 4; ks++) {                                        \
            MMA16816(Xdc0, ah0[ks], b[2*ks], b[2*ks+1]);                        \
            MMA16816(Xdc1, ah1[ks], b[2*ks], b[2*ks+1]);                        \
        }                                                                       \
        /* deferred fold of the OTHER set (inputs retired ~1 tile ago) */       \
        {                                                                       \
            float s;                                                            \
            s = Ydh0[0] + Ydc0[0];                                              \
            if (s > best[0]) { best[0] = s; bidx[0] = Ycode; }                  \
            s = Ydh0[1] + Ydc0[1];                                              \
            if (s > best[0]) { best[0] = s; bidx[0] = Ycode + 1; }              \
            s = Ydh0[2] + Ydc0[2];                                              \
            if (s > best[1]) { best[1] = s; bidx[1] = Ycode; }                  \
            s = Ydh0[3] + Ydc0[3];                                              \
            if (s > best[1]) { best[1] = s; bidx[1] = Ycode + 1; }              \
            s = Ydh1[0] + Ydc1[0];                                              \
            if (s > best[2]) { best[2] = s; bidx[2] = Ycode; }                  \
            s = Ydh1[1] + Ydc1[1];                                              \
            if (s > best[2]) { best[2] = s; bidx[2] = Ycode + 1; }              \
            s = Ydh1[2] + Ydc1[2];                                              \
            if (s > best[3]) { best[3] = s; bidx[3] = Ycode; }                  \
            s = Ydh1[3] + Ydc1[3];                                              \
            if (s > best[3]) { best[3] = s; bidx[3] = Ycode + 1; }              \
        }                                                                       \
    } while (0)

    const int nchunks = K / TKC;   // 8
    for (int c = 0; c < nchunks; c++) {
        __syncthreads();
        // ---- fused staging: fp32 emb -> bf16 hi/lo split + code norm ----
        {
            const float4* src = reinterpret_cast<const float4*>(
                emb + (size_t)(c * TKC + s_code) * DDIM + s_half * 32);
            char* dh_p = eh_sm + s_code * EPB + s_half * 64;
            char* dl_p = el_sm + s_code * EPB + s_half * 64;
            float nrm = 0.f;
#pragma unroll
            for (int q = 0; q < 8; q++) {
                float4 v = src[q];
                nrm += v.x * v.x + v.y * v.y + v.z * v.z + v.w * v.w;
                uint32_t h0 = pack_bf16x2(v.x, v.y);
                uint32_t h1 = pack_bf16x2(v.z, v.w);
                uint32_t l0 = pack_res(v.x, v.y, h0);
                uint32_t l1 = pack_res(v.z, v.w, h1);
                uint2 hp; hp.x = h0; hp.y = h1;
                uint2 lp; lp.x = l0; lp.y = l1;
                *reinterpret_cast<uint2*>(dh_p + q * 8) = hp;
                *reinterpret_cast<uint2*>(dl_p + q * 8) = lp;
            }
            nrm += __shfl_xor_sync(0xFFFFFFFFu, nrm, 1);
            if (s_half == 0) cns[s_code] = 0.5f * nrm;
        }
        __syncthreads();

#pragma unroll
        for (int nt = 0; nt < TKC / 8; nt += 2) {
            // even tile -> set A, folds B (previous tile)
            TILE_BODY(Adh0, Adh1, Adc0, Adc1, codeA,
                      Bdh0, Bdh1, Bdc0, Bdc1, codeB);
            {
                const int nt2 = nt + 1;
                // odd tile -> set B, folds A
                const int nt_save = nt;
                (void)nt_save;
                // reuse macro with nt = nt2
                {
                    int nt_backup = nt;
                    (void)nt_backup;
                }
                // expand manually with nt2
                uint32_t b[8];
                uint32_t lm_off = nt2 * 8 * EPB + lm_lane;
                LDMX4(b[0], b[1], b[2], b[3], eh_b + lm_off);
                LDMX4(b[4], b[5], b[6], b[7], eh_b + lm_off + 64);
                int lc0 = nt2 * 8 + qsub * 2;
                codeB = c * TKC + lc0;
                float2 cn = *reinterpret_cast<const float2*>(&cns[lc0]);
                Bdh0[0] = -cn.x; Bdh0[1] = -cn.y; Bdh0[2] = -cn.x; Bdh0[3] = -cn.y;
                Bdh1[0] = -cn.x; Bdh1[1] = -cn.y; Bdh1[2] = -cn.x; Bdh1[3] = -cn.y;
                Bdc0[0] = 0.f; Bdc0[1] = 0.f; Bdc0[2] = 0.f; Bdc0[3] = 0.f;
                Bdc1[0] = 0.f; Bdc1[1] = 0.f; Bdc1[2] = 0.f; Bdc1[3] = 0.f;
#pragma unroll
                for (int ks = 0; ks < 4; ks++) {
                    MMA16816(Bdh0, ah0[ks], b[2*ks], b[2*ks+1]);
                    MMA16816(Bdh1, ah1[ks], b[2*ks], b[2*ks+1]);
                    MMA16816(Bdc0, al0[ks], b[2*ks], b[2*ks+1]);
                    MMA16816(Bdc1, al1[ks], b[2*ks], b[2*ks+1]);
                }
                LDMX4(b[0], b[1], b[2], b[3], el_b + lm_off);
                LDMX4(b[4], b[5], b[6], b[7], el_b + lm_off + 64);
#pragma unroll
                for (int ks = 0; ks < 4; ks++) {
                    MMA16816(Bdc0, ah0[ks], b[2*ks], b[2*ks+1]);
                    MMA16816(Bdc1, ah1[ks], b[2*ks], b[2*ks+1]);
                }
                float s;
                s = Adh0[0] + Adc0[0];
                if (s > best[0]) { best[0] = s; bidx[0] = codeA; }
                s = Adh0[1] + Adc0[1];
                if (s > best[0]) { best[0] = s; bidx[0] = codeA + 1; }
                s = Adh0[2] + Adc0[2];
                if (s > best[1]) { best[1] = s; bidx[1] = codeA; }
                s = Adh0[3] + Adc0[3];
                if (s > best[1]) { best[1] = s; bidx[1] = codeA + 1; }
                s = Adh1[0] + Adc1[0];
                if (s > best[2]) { best[2] = s; bidx[2] = codeA; }
                s = Adh1[1] + Adc1[1];
                if (s > best[2]) { best[2] = s; bidx[2] = codeA + 1; }
                s = Adh1[2] + Adc1[2];
                if (s > best[3]) { best[3] = s; bidx[3] = codeA; }
                s = Adh1[3] + Adc1[3];
                if (s > best[3]) { best[3] = s; bidx[3] = codeA + 1; }
            }
        }
    }

    // final dangling fold: last tile wrote set B
    {
        float s;
        s = Bdh0[0] + Bdc0[0];
        if (s > best[0]) { best[0] = s; bidx[0] = codeB; }
        s = Bdh0[1] + Bdc0[1];
        if (s > best[0]) { best[0] = s; bidx[0] = codeB + 1; }
        s = Bdh0[2] + Bdc0[2];
        if (s > best[1]) { best[1] = s; bidx[1] = codeB; }
        s = Bdh0[3] + Bdc0[3];
        if (s > best[1]) { best[1] = s; bidx[1] = codeB + 1; }
        s = Bdh1[0] + Bdc1[0];
        if (s > best[2]) { best[2] = s; bidx[2] = codeB; }
        s = Bdh1[1] + Bdc1[1];
        if (s > best[2]) { best[2] = s; bidx[2] = codeB + 1; }
        s = Bdh1[2] + Bdc1[2];
        if (s > best[3]) { best[3] = s; bidx[3] = codeB; }
        s = Bdh1[3] + Bdc1[3];
        if (s > best[3]) { best[3] = s; bidx[3] = codeB + 1; }
    }

    // ---- quad-lane reduce (rows live in lanes 4q..4q+3), index tie-break ----
#pragma unroll
    for (int off = 1; off < 4; off <<= 1) {
#pragma unroll
        for (int r = 0; r < 4; r++) {
            float v = __shfl_xor_sync(0xFFFFFFFFu, best[r], off);
            int i = __shfl_xor_sync(0xFFFFFFFFu, bidx[r], off);
            if (v > best[r] || (v == best[r] && i < bidx[r])) {
                best[r] = v; bidx[r] = i;
            }
        }
    }
    if (qsub == 0) {
#pragma unroll
        for (int r = 0; r < 4; r++)
            finalIdx[wid * 32 + qid + r * 8] = bidx[r];
    }
    __syncthreads();

    if (write_idx)
        out[(size_t)N * DDIM + rowBase + tid] = (float)finalIdx[tid];

#pragma unroll
    for (int t = 0; t < 16; t++) {
        int idx = tid + t * 256;
        int row = idx >> 4;
        int c4 = idx & 15;
        float4 v = reinterpret_cast<const float4*>(
            emb + (size_t)finalIdx[row] * DDIM)[c4];
        reinterpret_cast<float4*>(out + (size_t)(rowBase + row) * DDIM)[c4] = v;
    }
}

extern "C" void kernel_launch(void* const* d_in, const int* in_sizes, int n_in,
                              void* d_out, int out_size) {
    const float* z = (const float*)d_in[0];
    const float* emb = (const float*)d_in[1];
    if (n_in >= 2 && in_sizes[1] > in_sizes[0]) {
        const float* t = z; z = emb; emb = t;
    }
    int zsize = in_sizes[0], esize = in_sizes[1];
    if (esize > zsize) { int t = zsize; zsize = esize; esize = t; }

    int N = zsize / DDIM;   // 65536
    int K = esize / DDIM;   // 1024
    float* out = (float*)d_out;
    int write_idx = (out_size >= N * DDIM + N) ? 1 : 0;

    vq_kernel<<<N / 256, 256>>>(z, emb, out, N, K, write_idx);
}